// round 14
// baseline (speedup 1.0000x reference)
#include <cuda_runtime.h>
#include <cuda_fp16.h>
#include <cstdint>
#include <math.h>

#define Bb   4
#define Ss   8
#define Ll   350
#define Dd   768
#define Pp   224
#define PP2  448
#define RMAX (Pp * 300)        // second_sep < 300 strictly

// ---------------------------------------------------------------------------
// Scratch (static device globals; no allocation allowed)
// ---------------------------------------------------------------------------
__device__ float g_scores[Pp * Ll];
__device__ float g_emb[PP2 * Dd];
__device__ float g_u2[PP2 * Dd];       // raw GEMM2 accumulator (pre-tanh)
__device__ int   g_poff[Pp + 1];
__device__ int   g_rowmap[RMAX];
__device__ __half g_Ah[RMAX * Dd];
__device__ __half g_Eh[PP2 * Dd];
__device__ __half g_W1h[Dd * Dd];
__device__ __half g_W2h[Dd * Dd];

__device__ __forceinline__ uint32_t smem_u32(const void* p) {
    uint32_t a;
    asm("{ .reg .u64 t; cvta.to.shared.u64 t, %1; cvt.u32.u64 %0, t; }"
        : "=r"(a) : "l"(p));
    return a;
}

__device__ __forceinline__ uint32_t pack2f(float a, float b) {
    __half2 h = __float22half2_rn(make_float2(a, b));
    return *reinterpret_cast<uint32_t*>(&h);
}

__device__ __forceinline__ float tanh_f(float x) {
    float y;
    asm("tanh.approx.f32 %0, %1;" : "=f"(y) : "f"(x));
    return y;
}

__device__ __forceinline__ void mma_fp16(float* c, const uint32_t* a,
                                         uint32_t b0, uint32_t b1) {
    asm volatile(
        "mma.sync.aligned.m16n8k16.row.col.f32.f16.f16.f32 "
        "{%0,%1,%2,%3}, {%4,%5,%6,%7}, {%8,%9}, {%0,%1,%2,%3};"
        : "+f"(c[0]), "+f"(c[1]), "+f"(c[2]), "+f"(c[3])
        : "r"(a[0]), "r"(a[1]), "r"(a[2]), "r"(a[3]), "r"(b0), "r"(b1));
}

#define LDSM4(r, a) \
    asm volatile("ldmatrix.sync.aligned.m8n8.x4.shared.b16 {%0,%1,%2,%3}, [%4];" \
        : "=r"((r)[0]), "=r"((r)[1]), "=r"((r)[2]), "=r"((r)[3]) : "r"(a))

#define CP16(dst, src) \
    asm volatile("cp.async.cg.shared.global [%0], [%1], 16;" \
                 :: "r"(dst), "l"(src) : "memory")
#define CP_COMMIT() asm volatile("cp.async.commit_group;" ::: "memory")
#define CP_WAIT1()  asm volatile("cp.async.wait_group 1;"  ::: "memory")

#define BKB     128            // bytes along k per stage (64 halves)
#define STRIDE  144
#define TILEB   18432          // 128 * 144
#define STAGEB  36864          // A | B
#define NST     3
#define SMEM_TOT (NST * STAGEB + 1024)

// ---------------------------------------------------------------------------
// k_init, three block roles in one launch:
//   blocks [0,672):     zero g_scores/g_u2, pair_embeddings copy,
//                       (block 0) global prefix offsets + rowmap
//   blocks [672,960):    W transpose + fp16 convert (288 = 12x12x2)
//   blocks [960,1632):   A compact+convert (pair p, 100-row chunk), local scan
// ---------------------------------------------------------------------------
__global__ void k_init(const float* __restrict__ x, const int* __restrict__ ss,
                       const float* __restrict__ W1, const float* __restrict__ W2,
                       float* __restrict__ out) {
    int bid = blockIdx.x;
    int tid = threadIdx.x;

    if (bid < 672) {
        int i = bid * 256 + tid;
        if (i < Pp * Ll) g_scores[i] = 0.f;
        g_u2[i * 2]     = 0.f;          // 672*256*2 = 344064 = PP2*Dd exactly
        g_u2[i * 2 + 1] = 0.f;
        if (i < Pp * Dd) {
            int p = i / Dd, d = i - p * Dd;
            out[i] = x[(size_t)p * Ll * Dd + d];
        }
        if (bid == 0) {
            __shared__ int sp[Pp];
            if (tid < Pp) sp[tid] = ss[tid];
            __syncthreads();
            if (tid == 0) {
                int a = 0;
                for (int p = 0; p < Pp; p++) { int v = sp[p]; sp[p] = a; a += v; }
                g_poff[Pp] = a;
            }
            __syncthreads();
            if (tid < Pp) {
                int base = sp[tid];
                g_poff[tid] = base;
                int cnt = ss[tid];
                int src = tid * Ll;
                for (int l = 0; l < cnt; l++) g_rowmap[base + l] = src + l;
            }
        }
    } else if (bid < 960) {
        __shared__ float s[64][65];
        int b = bid - 672;              // 288 = 12 x 12 x 2
        int kb = b % 12, nb = (b / 12) % 12, z = b / 144;
        int k0 = kb * 64, n0 = nb * 64;
        const float* W = z ? W2 : W1;
        __half* OH = z ? g_W2h : g_W1h;
        int nl = tid & 63, kl = tid >> 6;
        #pragma unroll
        for (int j = 0; j < 16; j++)
            s[kl + j * 4][nl] = W[(size_t)(k0 + kl + j * 4) * Dd + n0 + nl];
        __syncthreads();
        int q = tid & 31, nr = tid >> 5;
        #pragma unroll
        for (int j = 0; j < 8; j++) {
            int n = nr + j * 8;
            size_t off = (size_t)(n0 + n) * Dd + k0 + 2 * q;
            *reinterpret_cast<uint32_t*>(reinterpret_cast<char*>(OH) + off * 2) =
                pack2f(s[2 * q][n], s[2 * q + 1][n]);
        }
    } else {
        // A conversion role: block = (p, chunk of up to 100 rows)
        __shared__ int sp[256];
        int b = bid - 960;
        int p = b % Pp, chunk = b / Pp;          // chunk 0..2
        sp[tid] = (tid < Pp) ? ss[tid] : 0;
        __syncthreads();
        #pragma unroll
        for (int o = 1; o < Pp; o <<= 1) {
            int v = sp[tid];
            if (tid >= o && tid < Pp) v += sp[tid - o];
            __syncthreads();
            sp[tid] = v;
            __syncthreads();
        }
        int base = p ? sp[p - 1] : 0;
        int cnt  = sp[p] - base;                 // = ss[p]
        int l0c  = chunk * 100;
        int lend = min(cnt, l0c + 100);
        if (tid < 192 && l0c < lend) {
            int rows = lend - l0c;
            const float* src = x + ((size_t)p * Ll + l0c) * Dd + tid * 4;
            char* dst = reinterpret_cast<char*>(g_Ah)
                      + ((size_t)(base + l0c) * Dd + tid * 4) * 2;
            int lr = 0;
            for (; lr + 4 <= rows; lr += 4) {
                float4 v0 = *reinterpret_cast<const float4*>(src + (size_t)(lr)     * Dd);
                float4 v1 = *reinterpret_cast<const float4*>(src + (size_t)(lr + 1) * Dd);
                float4 v2 = *reinterpret_cast<const float4*>(src + (size_t)(lr + 2) * Dd);
                float4 v3 = *reinterpret_cast<const float4*>(src + (size_t)(lr + 3) * Dd);
                *reinterpret_cast<uint2*>(dst + (size_t)(lr)     * Dd * 2) =
                    make_uint2(pack2f(v0.x, v0.y), pack2f(v0.z, v0.w));
                *reinterpret_cast<uint2*>(dst + (size_t)(lr + 1) * Dd * 2) =
                    make_uint2(pack2f(v1.x, v1.y), pack2f(v1.z, v1.w));
                *reinterpret_cast<uint2*>(dst + (size_t)(lr + 2) * Dd * 2) =
                    make_uint2(pack2f(v2.x, v2.y), pack2f(v2.z, v2.w));
                *reinterpret_cast<uint2*>(dst + (size_t)(lr + 3) * Dd * 2) =
                    make_uint2(pack2f(v3.x, v3.y), pack2f(v3.z, v3.w));
            }
            for (; lr < rows; lr++) {
                float4 v0 = *reinterpret_cast<const float4*>(src + (size_t)lr * Dd);
                *reinterpret_cast<uint2*>(dst + (size_t)lr * Dd * 2) =
                    make_uint2(pack2f(v0.x, v0.y), pack2f(v0.z, v0.w));
            }
        }
    }
}

// ---------------------------------------------------------------------------
// GEMM1 (scores): persistent fused HMMA, BK=64, NST=3, cp.async ring running
// continuously ACROSS items. 296 CTAs (2/SM, 110KB smem co-residency
// preserved — the R10 failure mode was smem growth, not persistence).
// ---------------------------------------------------------------------------
__global__ __launch_bounds__(256, 2) void k_gemm1(
    const float* __restrict__ bvec, const float* __restrict__ vvec)
{
    extern __shared__ char smem[];
    int tid = threadIdx.x;
    int R = g_poff[Pp];
    int ntiles = (R + 127) >> 7;
    int total = ntiles * 6;
    int bid = blockIdx.x;
    int gstep = gridDim.x;
    if (bid >= total) return;

    const char* AHc = reinterpret_cast<const char*>(g_Ah);
    const char* WHc = reinterpret_cast<const char*>(g_W1h);

    uint32_t sb = smem_u32(smem);

    // fill lanes: chunk q (16B of the 128B k-stage), rows rb+32j
    int q = tid & 7, rb = tid >> 3;
    uint32_t pd[4];
    #pragma unroll
    for (int j = 0; j < 4; j++)
        pd[j] = sb + (rb + j * 32) * STRIDE + q * 16;

    // ---- ring fill frame (runs 2 stages ahead, across items) ----
    int fill_idx = bid, fill_kc = 0, fill_st = 0;
    uint32_t f_a[4], f_b[4];
    auto setframe = [&](int idx) {
        int l0 = (idx % ntiles) << 7;
        int nc = idx / ntiles;
        #pragma unroll
        for (int j = 0; j < 4; j++) {
            int row = rb + j * 32;
            int gr = l0 + row; if (gr >= R) gr = R - 1;
            f_a[j] = (uint32_t)gr * (Dd * 2) + q * 16;
            f_b[j] = (uint32_t)(nc * 128 + row) * (Dd * 2) + q * 16;
        }
    };
    setframe(fill_idx);

    auto FILLSEQ = [&]() {
        uint32_t stg = fill_st * STAGEB;
        int ko = fill_kc * BKB;
        #pragma unroll
        for (int j = 0; j < 4; j++) {
            CP16(pd[j] + stg,         AHc + f_a[j] + ko);
            CP16(pd[j] + stg + TILEB, WHc + f_b[j] + ko);
        }
        CP_COMMIT();
        fill_st++; if (fill_st == NST) fill_st = 0;
        if (++fill_kc == 12) {
            fill_kc = 0;
            fill_idx += gstep;
            if (fill_idx < total) setframe(fill_idx);
        }
    };

    int warp = tid >> 5, lane = tid & 31;
    int g = lane >> 2, t = lane & 3;
    int m0 = (warp >> 1) * 32;
    int wn = warp & 1;
    int n0w = wn * 64;

    int aoff = ((lane & 7) + ((lane >> 3) & 1) * 8) * STRIDE + (lane >> 4) * 16;
    int boff = ((lane >> 4) * 8 + (lane & 7)) * STRIDE + ((lane >> 3) & 1) * 16;

    float acc[2][8][4];

    auto COMPUTE = [&](int st) {
        uint32_t base = sb + st * STAGEB;
        #pragma unroll
        for (int kk = 0; kk < 64; kk += 16) {
            uint32_t ah[2][4];
            #pragma unroll
            for (int sm = 0; sm < 2; sm++)
                LDSM4(ah[sm], base + (m0 + sm * 16) * STRIDE + aoff + kk * 2);
            #pragma unroll
            for (int ns2 = 0; ns2 < 4; ns2++) {
                uint32_t bh[4];
                LDSM4(bh, base + TILEB + (n0w + ns2 * 16) * STRIDE + boff + kk * 2);
                #pragma unroll
                for (int sm = 0; sm < 2; sm++) {
                    mma_fp16(acc[sm][2 * ns2],     ah[sm], bh[0], bh[1]);
                    mma_fp16(acc[sm][2 * ns2 + 1], ah[sm], bh[2], bh[3]);
                }
            }
        }
    };

    int items = (total - 1 - bid) / gstep + 1;
    int fills_left = items * 12;
    FILLSEQ(); fills_left--;
    FILLSEQ(); fills_left--;

    int comp_st = 0;
    float* red = reinterpret_cast<float*>(smem + NST * STAGEB);

    for (int item = bid; item < total; item += gstep) {
        #pragma unroll
        for (int sm = 0; sm < 2; sm++)
            #pragma unroll
            for (int ns = 0; ns < 8; ns++)
                #pragma unroll
                for (int j = 0; j < 4; j++) acc[sm][ns][j] = 0.f;

        #pragma unroll 1
        for (int kc = 0; kc < 12; kc++) {
            CP_WAIT1();
            __syncthreads();
            COMPUTE(comp_st);
            comp_st++; if (comp_st == NST) comp_st = 0;
            if (fills_left > 0) { FILLSEQ(); fills_left--; }
            else CP_COMMIT();
        }

        // fused epilogue (overlaps the 2 in-flight fills + co-resident CTA)
        int l0 = (item % ntiles) << 7;
        int nc = item / ntiles;
        float partial[4] = {0.f, 0.f, 0.f, 0.f};
        #pragma unroll
        for (int sm = 0; sm < 2; sm++)
            #pragma unroll
            for (int ns = 0; ns < 8; ns++) {
                int col = nc * 128 + n0w + ns * 8 + 2 * t;
                float bb0 = __ldg(&bvec[col]), bb1 = __ldg(&bvec[col + 1]);
                float vv0 = __ldg(&vvec[col]), vv1 = __ldg(&vvec[col + 1]);
                partial[sm * 2 + 0] += tanh_f(acc[sm][ns][0] + bb0) * vv0
                                     + tanh_f(acc[sm][ns][1] + bb1) * vv1;
                partial[sm * 2 + 1] += tanh_f(acc[sm][ns][2] + bb0) * vv0
                                     + tanh_f(acc[sm][ns][3] + bb1) * vv1;
            }
        #pragma unroll
        for (int j = 0; j < 4; j++) {
            partial[j] += __shfl_xor_sync(0xffffffffu, partial[j], 1);
            partial[j] += __shfl_xor_sync(0xffffffffu, partial[j], 2);
        }
        __syncthreads();
        if (t == 0) {
            red[wn * 128 + m0 + g]      = partial[0];
            red[wn * 128 + m0 + 8 + g]  = partial[1];
            red[wn * 128 + m0 + 16 + g] = partial[2];
            red[wn * 128 + m0 + 24 + g] = partial[3];
        }
        __syncthreads();
        if (tid < 128) {
            int r = l0 + tid;
            if (r < R) {
                float val = red[tid] + red[128 + tid];
                atomicAdd(&g_scores[g_rowmap[r]], val);
            }
        }
    }
}

// ---------------------------------------------------------------------------
// GEMM2 (raw): grid (4 row tiles, 6 nc, 4 K-quarters), K=192 (3 stages),
// fp32 partials atomicAdd'ed to g_u2 (K-split is linear; tanh deferred).
// ---------------------------------------------------------------------------
__global__ __launch_bounds__(256) void k_gemm2() {
    extern __shared__ char smem[];
    int tid = threadIdx.x;
    int l0 = blockIdx.x * 128;
    int nc = blockIdx.y;
    int kbase = blockIdx.z * 384;        // bytes along k

    uint32_t sb = smem_u32(smem);

    int q = tid & 7, rb = tid >> 3;
    const char *pa[4], *pb[4];
    uint32_t pd[4];
    #pragma unroll
    for (int j = 0; j < 4; j++) {
        int row = rb + j * 32;
        int gr = l0 + row; if (gr >= PP2) gr = PP2 - 1;
        pa[j] = reinterpret_cast<const char*>(g_Eh + (size_t)gr * Dd) + kbase + q * 16;
        pb[j] = reinterpret_cast<const char*>(g_W2h + (size_t)(nc * 128 + row) * Dd) + kbase + q * 16;
        pd[j] = sb + row * STRIDE + q * 16;
    }

    auto FILL = [&](int s, int kc) {
        uint32_t stg = s * STAGEB;
        int ko = kc * BKB;
        #pragma unroll
        for (int j = 0; j < 4; j++) {
            CP16(pd[j] + stg,         pa[j] + ko);
            CP16(pd[j] + stg + TILEB, pb[j] + ko);
        }
    };

    int warp = tid >> 5, lane = tid & 31;
    int g = lane >> 2, t = lane & 3;
    int m0 = (warp >> 1) * 32;
    int wn = warp & 1;
    int n0w = wn * 64;

    int aoff = ((lane & 7) + ((lane >> 3) & 1) * 8) * STRIDE + (lane >> 4) * 16;
    int boff = ((lane >> 4) * 8 + (lane & 7)) * STRIDE + ((lane >> 3) & 1) * 16;

    float acc[2][8][4];
    #pragma unroll
    for (int sm = 0; sm < 2; sm++)
        #pragma unroll
        for (int ns = 0; ns < 8; ns++)
            #pragma unroll
            for (int j = 0; j < 4; j++) acc[sm][ns][j] = 0.f;

    auto COMPUTE = [&](int st) {
        uint32_t base = sb + st * STAGEB;
        #pragma unroll
        for (int kk = 0; kk < 64; kk += 16) {
            uint32_t ah[2][4];
            #pragma unroll
            for (int sm = 0; sm < 2; sm++)
                LDSM4(ah[sm], base + (m0 + sm * 16) * STRIDE + aoff + kk * 2);
            #pragma unroll
            for (int ns2 = 0; ns2 < 4; ns2++) {
                uint32_t bh[4];
                LDSM4(bh, base + TILEB + (n0w + ns2 * 16) * STRIDE + boff + kk * 2);
                #pragma unroll
                for (int sm = 0; sm < 2; sm++) {
                    mma_fp16(acc[sm][2 * ns2],     ah[sm], bh[0], bh[1]);
                    mma_fp16(acc[sm][2 * ns2 + 1], ah[sm], bh[2], bh[3]);
                }
            }
        }
    };

    FILL(0, 0); CP_COMMIT();
    FILL(1, 1); CP_COMMIT();
    for (int kc = 0; kc < 3; kc++) {
        CP_WAIT1();
        __syncthreads();
        COMPUTE(kc);
        if (kc < 1) FILL(2, 2);
        CP_COMMIT();
    }

    #pragma unroll
    for (int sm = 0; sm < 2; sm++)
        #pragma unroll
        for (int ns = 0; ns < 8; ns++) {
            int row0 = l0 + m0 + sm * 16 + g;
            int col  = nc * 128 + n0w + ns * 8 + 2 * t;
            if (row0 < PP2) {
                atomicAdd(&g_u2[(size_t)row0 * Dd + col],     acc[sm][ns][0]);
                atomicAdd(&g_u2[(size_t)row0 * Dd + col + 1], acc[sm][ns][1]);
            }
            if (row0 + 8 < PP2) {
                atomicAdd(&g_u2[(size_t)(row0 + 8) * Dd + col],     acc[sm][ns][2]);
                atomicAdd(&g_u2[(size_t)(row0 + 8) * Dd + col + 1], acc[sm][ns][3]);
            }
        }
}

// ---------------------------------------------------------------------------
// Masked softmax pooling reading fp16 g_Ah (compact rows). 192 threads,
// thread t owns d = 4t..4t+3 (8B loads), rows unrolled x8 (64B in flight).
// ---------------------------------------------------------------------------
__global__ __launch_bounds__(192) void k_pool(const int* __restrict__ fs,
                                              const int* __restrict__ ssp)
{
    int p   = blockIdx.y;
    int sgi = blockIdx.x;
    int f = fs[p], s2 = ssp[p];
    int lo = sgi ? f + 1 : 1;
    int hi = sgi ? s2 : f;
    int cnt = hi - lo;                      // 4..148

    __shared__ float w[152];
    __shared__ float wred[8];
    __shared__ float bc;
    int tid = threadIdx.x;
    int lane = tid & 31, wid = tid >> 5;

    const float* sc = g_scores + p * Ll + lo;

    float lm = (tid < cnt) ? sc[tid] : -1e30f;
    #pragma unroll
    for (int o = 16; o > 0; o >>= 1) lm = fmaxf(lm, __shfl_xor_sync(~0u, lm, o));
    if (lane == 0) wred[wid] = lm;
    __syncthreads();
    if (tid == 0) {
        float m = wred[0];
        #pragma unroll
        for (int j = 1; j < 6; j++) m = fmaxf(m, wred[j]);
        bc = m;
    }
    __syncthreads();
    float smax = bc;

    float le = 0.f;
    if (tid < cnt) { float e = __expf(sc[tid] - smax); w[tid] = e; le = e; }
    #pragma unroll
    for (int o = 16; o > 0; o >>= 1) le += __shfl_xor_sync(~0u, le, o);
    if (lane == 0) wred[wid] = le;
    __syncthreads();
    if (tid == 0) {
        float s = 0.f;
        #pragma unroll
        for (int j = 1; j < 6; j++) s += wred[j];
        bc = 1.0f / (s + wred[0]);
    }
    __syncthreads();
    float inv = bc;
    if (tid < cnt) w[tid] *= inv;
    __syncthreads();

    int r0 = g_poff[p] + lo;
    const char* xr = reinterpret_cast<const char*>(g_Ah) + ((size_t)r0 * Dd) * 2 + tid * 8;
    float e0 = 0.f, e1 = 0.f, e2 = 0.f, e3 = 0.f;
    int i = 0;
    for (; i + 8 <= cnt; i += 8) {
        uint2 u[8];
        #pragma unroll
        for (int j = 0; j < 8; j++)
            u[j] = *reinterpret_cast<const uint2*>(xr + (size_t)(i + j) * Dd * 2);
        #pragma unroll
        for (int j = 0; j < 8; j++) {
            float wj = w[i + j];
            float2 a0 = __half22float2(*reinterpret_cast<__half2*>(&u[j].x));
            float2 a1 = __half22float2(*reinterpret_cast<__half2*>(&u[j].y));
            e0 += wj * a0.x; e1 += wj * a0.y; e2 += wj * a1.x; e3 += wj * a1.y;
        }
    }
    for (; i < cnt; i++) {
        uint2 u0 = *reinterpret_cast<const uint2*>(xr + (size_t)i * Dd * 2);
        float w0 = w[i];
        float2 a0 = __half22float2(*reinterpret_cast<__half2*>(&u0.x));
        float2 a1 = __half22float2(*reinterpret_cast<__half2*>(&u0.y));
        e0 += w0 * a0.x; e1 += w0 * a0.y; e2 += w0 * a1.x; e3 += w0 * a1.y;
    }

    int rowi = 2 * p + sgi;
    float4* er = reinterpret_cast<float4*>(g_emb + (size_t)rowi * Dd);
    er[tid] = make_float4(e0, e1, e2, e3);
    *reinterpret_cast<uint2*>(
        reinterpret_cast<char*>(g_Eh) + ((size_t)rowi * Dd) * 2 + tid * 8) =
        make_uint2(pack2f(e0, e1), pack2f(e2, e3));
}

// ---------------------------------------------------------------------------
// out2: epilogue of GEMM2 (tanh(u2+b2)@v2 for this segment's 14 rows) +
// segment softmax + weighted sum.
// ---------------------------------------------------------------------------
__global__ __launch_bounds__(256) void k_out2(const float* __restrict__ b2,
                                              const float* __restrict__ v2,
                                              float* __restrict__ out) {
    int seg = blockIdx.x;
    int tid = threadIdx.x;
    int lane = tid & 31, wid = tid >> 5;
    __shared__ int   mem[14];
    __shared__ float sscore[14];
    __shared__ float wv[14];

    if (tid == 0) {
        int c = 0;
        for (int idx = 0; idx < PP2; idx++) {
            int pp = idx >> 1, cc = idx & 1;
            int z = pp / 56, r = pp % 56, j = r / 7, m = r % 7;
            int k = m + (m >= j ? 1 : 0);
            int sg = z * 8 + (cc == 0 ? j : k);
            if (sg == seg && c < 14) mem[c++] = idx;
        }
    }
    __syncthreads();

    #pragma unroll
    for (int ii = 0; ii < 2; ii++) {
        int i = wid + ii * 8;
        if (i < 14) {
            const float* ur = g_u2 + (size_t)mem[i] * Dd;
            float acc = 0.f;
            for (int d = lane; d < Dd; d += 32)
                acc += tanh_f(ur[d] + __ldg(&b2[d])) * __ldg(&v2[d]);
            #pragma unroll
            for (int o = 16; o > 0; o >>= 1)
                acc += __shfl_xor_sync(~0u, acc, o);
            if (lane == 0) sscore[i] = acc;
        }
    }
    __syncthreads();

    if (tid == 0) {
        float mx = -1e30f;
        for (int i = 0; i < 14; i++) mx = fmaxf(mx, sscore[i]);
        float den = 0.f;
        for (int i = 0; i < 14; i++) {
            float e = __expf(sscore[i] - mx);
            wv[i] = e;
            den += e;
        }
        float inv = 1.f / den;
        for (int i = 0; i < 14; i++) wv[i] *= inv;
    }
    __syncthreads();

    for (int d = tid; d < Dd; d += 256) {
        float a = 0.f;
        #pragma unroll
        for (int i = 0; i < 14; i++)
            a += wv[i] * g_emb[(size_t)mem[i] * Dd + d];
        out[Pp * Dd + seg * Dd + d] = a;
    }
}

// ---------------------------------------------------------------------------
// Launch
// ---------------------------------------------------------------------------
extern "C" void kernel_launch(void* const* d_in, const int* in_sizes, int n_in,
                              void* d_out, int out_size) {
    const float* x   = (const float*)d_in[0];
    const int*   fs  = (const int*)  d_in[1];
    const int*   ss  = (const int*)  d_in[2];
    const float* W1  = (const float*)d_in[3];
    const float* b1  = (const float*)d_in[4];
    const float* v1  = (const float*)d_in[5];
    const float* W2  = (const float*)d_in[7];
    const float* b2  = (const float*)d_in[8];
    const float* v2  = (const float*)d_in[9];
    float* out = (float*)d_out;

    static bool attr_done = false;
    if (!attr_done) {
        cudaFuncSetAttribute(k_gemm1,
            cudaFuncAttributeMaxDynamicSharedMemorySize, SMEM_TOT);
        cudaFuncSetAttribute(k_gemm2,
            cudaFuncAttributeMaxDynamicSharedMemorySize, SMEM_TOT);
        attr_done = true;
    }

    k_init<<<1632, 256>>>(x, ss, W1, W2, out);

    k_gemm1<<<296, 256, SMEM_TOT>>>(b1, v1);

    k_pool<<<dim3(2, Pp), 192>>>(fs, ss);

    k_gemm2<<<dim3(4, 6, 4), 256, SMEM_TOT>>>();

    k_out2<<<Bb * Ss, 256>>>(b2, v2, out);
}

// round 15
// speedup vs baseline: 1.0218x; 1.0218x over previous
#include <cuda_runtime.h>
#include <cuda_fp16.h>
#include <cstdint>
#include <math.h>

#define Bb   4
#define Ss   8
#define Ll   350
#define Dd   768
#define Pp   224
#define PP2  448
#define RMAX (Pp * 300)        // second_sep < 300 strictly

// ---------------------------------------------------------------------------
// Scratch (static device globals; no allocation allowed)
// ---------------------------------------------------------------------------
__device__ float g_scores[Pp * Ll];
__device__ float g_emb[PP2 * Dd];
__device__ float g_u2[PP2 * Dd];       // raw GEMM2 accumulator (pre-tanh)
__device__ int   g_poff[Pp + 1];
__device__ int   g_rowmap[RMAX];
__device__ __half g_Ah[RMAX * Dd];
__device__ __half g_Eh[PP2 * Dd];
__device__ __half g_W1h[Dd * Dd];
__device__ __half g_W2h[Dd * Dd];

__device__ __forceinline__ uint32_t smem_u32(const void* p) {
    uint32_t a;
    asm("{ .reg .u64 t; cvta.to.shared.u64 t, %1; cvt.u32.u64 %0, t; }"
        : "=r"(a) : "l"(p));
    return a;
}

__device__ __forceinline__ uint32_t pack2f(float a, float b) {
    __half2 h = __float22half2_rn(make_float2(a, b));
    return *reinterpret_cast<uint32_t*>(&h);
}

__device__ __forceinline__ float tanh_f(float x) {
    float y;
    asm("tanh.approx.f32 %0, %1;" : "=f"(y) : "f"(x));
    return y;
}

__device__ __forceinline__ void mma_fp16(float* c, const uint32_t* a,
                                         uint32_t b0, uint32_t b1) {
    asm volatile(
        "mma.sync.aligned.m16n8k16.row.col.f32.f16.f16.f32 "
        "{%0,%1,%2,%3}, {%4,%5,%6,%7}, {%8,%9}, {%0,%1,%2,%3};"
        : "+f"(c[0]), "+f"(c[1]), "+f"(c[2]), "+f"(c[3])
        : "r"(a[0]), "r"(a[1]), "r"(a[2]), "r"(a[3]), "r"(b0), "r"(b1));
}

#define LDSM4(r, a) \
    asm volatile("ldmatrix.sync.aligned.m8n8.x4.shared.b16 {%0,%1,%2,%3}, [%4];" \
        : "=r"((r)[0]), "=r"((r)[1]), "=r"((r)[2]), "=r"((r)[3]) : "r"(a))

#define CP16(dst, src) \
    asm volatile("cp.async.cg.shared.global [%0], [%1], 16;" \
                 :: "r"(dst), "l"(src) : "memory")
#define CP_COMMIT() asm volatile("cp.async.commit_group;" ::: "memory")
#define CP_WAIT1()  asm volatile("cp.async.wait_group 1;"  ::: "memory")

#define BKB     128            // bytes along k per stage (64 halves)
#define STRIDE  144
#define TILEB   18432          // 128 * 144
#define STAGEB  36864          // A | B
#define NST     3
#define SMEM_TOT (NST * STAGEB + 1024)

// ---------------------------------------------------------------------------
// k_init, three block roles in one launch:
//   blocks [0,672):     zero g_scores/g_u2, pair_embeddings copy,
//                       (block 0) global prefix offsets + rowmap
//   blocks [672,960):    W transpose + fp16 convert (288 = 12x12x2)
//   blocks [960,1632):   A compact+convert (pair p, 100-row chunk), local scan
// ---------------------------------------------------------------------------
__global__ void k_init(const float* __restrict__ x, const int* __restrict__ ss,
                       const float* __restrict__ W1, const float* __restrict__ W2,
                       float* __restrict__ out) {
    int bid = blockIdx.x;
    int tid = threadIdx.x;

    if (bid < 672) {
        int i = bid * 256 + tid;
        if (i < Pp * Ll) g_scores[i] = 0.f;
        g_u2[i * 2]     = 0.f;          // 672*256*2 = 344064 = PP2*Dd exactly
        g_u2[i * 2 + 1] = 0.f;
        if (i < Pp * Dd) {
            int p = i / Dd, d = i - p * Dd;
            out[i] = x[(size_t)p * Ll * Dd + d];
        }
        if (bid == 0) {
            __shared__ int sp[Pp];
            if (tid < Pp) sp[tid] = ss[tid];
            __syncthreads();
            if (tid == 0) {
                int a = 0;
                for (int p = 0; p < Pp; p++) { int v = sp[p]; sp[p] = a; a += v; }
                g_poff[Pp] = a;
            }
            __syncthreads();
            if (tid < Pp) {
                int base = sp[tid];
                g_poff[tid] = base;
                int cnt = ss[tid];
                int src = tid * Ll;
                for (int l = 0; l < cnt; l++) g_rowmap[base + l] = src + l;
            }
        }
    } else if (bid < 960) {
        __shared__ float s[64][65];
        int b = bid - 672;              // 288 = 12 x 12 x 2
        int kb = b % 12, nb = (b / 12) % 12, z = b / 144;
        int k0 = kb * 64, n0 = nb * 64;
        const float* W = z ? W2 : W1;
        __half* OH = z ? g_W2h : g_W1h;
        int nl = tid & 63, kl = tid >> 6;
        #pragma unroll
        for (int j = 0; j < 16; j++)
            s[kl + j * 4][nl] = W[(size_t)(k0 + kl + j * 4) * Dd + n0 + nl];
        __syncthreads();
        int q = tid & 31, nr = tid >> 5;
        #pragma unroll
        for (int j = 0; j < 8; j++) {
            int n = nr + j * 8;
            size_t off = (size_t)(n0 + n) * Dd + k0 + 2 * q;
            *reinterpret_cast<uint32_t*>(reinterpret_cast<char*>(OH) + off * 2) =
                pack2f(s[2 * q][n], s[2 * q + 1][n]);
        }
    } else {
        // A conversion role: block = (p, chunk of up to 100 rows)
        __shared__ int sp[256];
        int b = bid - 960;
        int p = b % Pp, chunk = b / Pp;          // chunk 0..2
        sp[tid] = (tid < Pp) ? ss[tid] : 0;
        __syncthreads();
        #pragma unroll
        for (int o = 1; o < Pp; o <<= 1) {
            int v = sp[tid];
            if (tid >= o && tid < Pp) v += sp[tid - o];
            __syncthreads();
            sp[tid] = v;
            __syncthreads();
        }
        int base = p ? sp[p - 1] : 0;
        int cnt  = sp[p] - base;                 // = ss[p]
        int l0c  = chunk * 100;
        int lend = min(cnt, l0c + 100);
        if (tid < 192 && l0c < lend) {
            int rows = lend - l0c;
            const float* src = x + ((size_t)p * Ll + l0c) * Dd + tid * 4;
            char* dst = reinterpret_cast<char*>(g_Ah)
                      + ((size_t)(base + l0c) * Dd + tid * 4) * 2;
            int lr = 0;
            for (; lr + 4 <= rows; lr += 4) {
                float4 v0 = *reinterpret_cast<const float4*>(src + (size_t)(lr)     * Dd);
                float4 v1 = *reinterpret_cast<const float4*>(src + (size_t)(lr + 1) * Dd);
                float4 v2 = *reinterpret_cast<const float4*>(src + (size_t)(lr + 2) * Dd);
                float4 v3 = *reinterpret_cast<const float4*>(src + (size_t)(lr + 3) * Dd);
                *reinterpret_cast<uint2*>(dst + (size_t)(lr)     * Dd * 2) =
                    make_uint2(pack2f(v0.x, v0.y), pack2f(v0.z, v0.w));
                *reinterpret_cast<uint2*>(dst + (size_t)(lr + 1) * Dd * 2) =
                    make_uint2(pack2f(v1.x, v1.y), pack2f(v1.z, v1.w));
                *reinterpret_cast<uint2*>(dst + (size_t)(lr + 2) * Dd * 2) =
                    make_uint2(pack2f(v2.x, v2.y), pack2f(v2.z, v2.w));
                *reinterpret_cast<uint2*>(dst + (size_t)(lr + 3) * Dd * 2) =
                    make_uint2(pack2f(v3.x, v3.y), pack2f(v3.z, v3.w));
            }
            for (; lr < rows; lr++) {
                float4 v0 = *reinterpret_cast<const float4*>(src + (size_t)lr * Dd);
                *reinterpret_cast<uint2*>(dst + (size_t)lr * Dd * 2) =
                    make_uint2(pack2f(v0.x, v0.y), pack2f(v0.z, v0.w));
            }
        }
    }
}

// ---------------------------------------------------------------------------
// GEMM1 (scores): wave-based fused HMMA (best measured form, R13), BK=64,
// NST=3 cp.async, ldmatrix. grid (row tiles, 6 nc), K=768 (12 stages),
// fused tanh epilogue -> atomicAdd per-row partials.
// 110KB smem -> 2 CTAs/SM co-residency (protected). Persistence: rejected
// twice (R10, R14) — do not retry.
// ---------------------------------------------------------------------------
__global__ __launch_bounds__(256) void k_gemm1(
    const float* __restrict__ bvec, const float* __restrict__ vvec)
{
    extern __shared__ char smem[];
    int tid = threadIdx.x;
    int l0 = blockIdx.x * 128;
    int nc = blockIdx.y;

    int R = g_poff[Pp];
    if (l0 >= R) return;

    uint32_t sb = smem_u32(smem);

    // copy lanes: chunk q (16B of the 128B k-row), rows rb, rb+32, rb+64, rb+96
    int q = tid & 7, rb = tid >> 3;
    const char *pa[4], *pb[4];
    uint32_t pd[4];
    #pragma unroll
    for (int j = 0; j < 4; j++) {
        int row = rb + j * 32;
        int gr = l0 + row; if (gr >= R) gr = R - 1;
        pa[j] = reinterpret_cast<const char*>(g_Ah + (size_t)gr * Dd) + q * 16;
        pb[j] = reinterpret_cast<const char*>(g_W1h + (size_t)(nc * 128 + row) * Dd) + q * 16;
        pd[j] = sb + row * STRIDE + q * 16;
    }

    auto FILL = [&](int s, int kc) {
        uint32_t stg = s * STAGEB;
        int ko = kc * BKB;
        #pragma unroll
        for (int j = 0; j < 4; j++) {
            CP16(pd[j] + stg,         pa[j] + ko);
            CP16(pd[j] + stg + TILEB, pb[j] + ko);
        }
    };

    int warp = tid >> 5, lane = tid & 31;
    int g = lane >> 2, t = lane & 3;
    int m0 = (warp >> 1) * 32;
    int wn = warp & 1;
    int n0w = wn * 64;

    int aoff = ((lane & 7) + ((lane >> 3) & 1) * 8) * STRIDE + (lane >> 4) * 16;
    int boff = ((lane >> 4) * 8 + (lane & 7)) * STRIDE + ((lane >> 3) & 1) * 16;

    float acc[2][8][4];
    #pragma unroll
    for (int sm = 0; sm < 2; sm++)
        #pragma unroll
        for (int ns = 0; ns < 8; ns++)
            #pragma unroll
            for (int j = 0; j < 4; j++) acc[sm][ns][j] = 0.f;

    auto COMPUTE = [&](int st) {
        uint32_t base = sb + st * STAGEB;
        #pragma unroll
        for (int kk = 0; kk < 64; kk += 16) {
            uint32_t ah[2][4];
            #pragma unroll
            for (int sm = 0; sm < 2; sm++)
                LDSM4(ah[sm], base + (m0 + sm * 16) * STRIDE + aoff + kk * 2);
            #pragma unroll
            for (int ns2 = 0; ns2 < 4; ns2++) {
                uint32_t bh[4];
                LDSM4(bh, base + TILEB + (n0w + ns2 * 16) * STRIDE + boff + kk * 2);
                #pragma unroll
                for (int sm = 0; sm < 2; sm++) {
                    mma_fp16(acc[sm][2 * ns2],     ah[sm], bh[0], bh[1]);
                    mma_fp16(acc[sm][2 * ns2 + 1], ah[sm], bh[2], bh[3]);
                }
            }
        }
    };

    FILL(0, 0); CP_COMMIT();
    FILL(1, 1); CP_COMMIT();

    for (int kc = 0; kc < 12; kc++) {
        CP_WAIT1();
        __syncthreads();
        COMPUTE(kc % 3);
        if (kc < 10) FILL((kc + 2) % 3, kc + 2);
        CP_COMMIT();
    }

    // fused epilogue: tanh(acc + b) * v -> per-row partials (this n-chunk)
    float partial[4] = {0.f, 0.f, 0.f, 0.f};
    #pragma unroll
    for (int sm = 0; sm < 2; sm++)
        #pragma unroll
        for (int ns = 0; ns < 8; ns++) {
            int col = nc * 128 + n0w + ns * 8 + 2 * t;
            float bb0 = __ldg(&bvec[col]), bb1 = __ldg(&bvec[col + 1]);
            float vv0 = __ldg(&vvec[col]), vv1 = __ldg(&vvec[col + 1]);
            partial[sm * 2 + 0] += tanh_f(acc[sm][ns][0] + bb0) * vv0
                                 + tanh_f(acc[sm][ns][1] + bb1) * vv1;
            partial[sm * 2 + 1] += tanh_f(acc[sm][ns][2] + bb0) * vv0
                                 + tanh_f(acc[sm][ns][3] + bb1) * vv1;
        }

    #pragma unroll
    for (int j = 0; j < 4; j++) {
        partial[j] += __shfl_xor_sync(0xffffffffu, partial[j], 1);
        partial[j] += __shfl_xor_sync(0xffffffffu, partial[j], 2);
    }
    float* red = reinterpret_cast<float*>(smem + NST * STAGEB);
    __syncthreads();
    if (t == 0) {
        red[wn * 128 + m0 + g]      = partial[0];
        red[wn * 128 + m0 + 8 + g]  = partial[1];
        red[wn * 128 + m0 + 16 + g] = partial[2];
        red[wn * 128 + m0 + 24 + g] = partial[3];
    }
    __syncthreads();
    if (tid < 128) {
        int r = l0 + tid;
        if (r < R) {
            float val = red[tid] + red[128 + tid];
            atomicAdd(&g_scores[g_rowmap[r]], val);
        }
    }
}

// ---------------------------------------------------------------------------
// GEMM2 (raw): grid (4 row tiles, 6 nc, 4 K-quarters), K=192 (3 stages),
// fp32 partials atomicAdd'ed to g_u2 (K-split is linear; tanh deferred).
// ---------------------------------------------------------------------------
__global__ __launch_bounds__(256) void k_gemm2() {
    extern __shared__ char smem[];
    int tid = threadIdx.x;
    int l0 = blockIdx.x * 128;
    int nc = blockIdx.y;
    int kbase = blockIdx.z * 384;        // bytes along k

    uint32_t sb = smem_u32(smem);

    int q = tid & 7, rb = tid >> 3;
    const char *pa[4], *pb[4];
    uint32_t pd[4];
    #pragma unroll
    for (int j = 0; j < 4; j++) {
        int row = rb + j * 32;
        int gr = l0 + row; if (gr >= PP2) gr = PP2 - 1;
        pa[j] = reinterpret_cast<const char*>(g_Eh + (size_t)gr * Dd) + kbase + q * 16;
        pb[j] = reinterpret_cast<const char*>(g_W2h + (size_t)(nc * 128 + row) * Dd) + kbase + q * 16;
        pd[j] = sb + row * STRIDE + q * 16;
    }

    auto FILL = [&](int s, int kc) {
        uint32_t stg = s * STAGEB;
        int ko = kc * BKB;
        #pragma unroll
        for (int j = 0; j < 4; j++) {
            CP16(pd[j] + stg,         pa[j] + ko);
            CP16(pd[j] + stg + TILEB, pb[j] + ko);
        }
    };

    int warp = tid >> 5, lane = tid & 31;
    int g = lane >> 2, t = lane & 3;
    int m0 = (warp >> 1) * 32;
    int wn = warp & 1;
    int n0w = wn * 64;

    int aoff = ((lane & 7) + ((lane >> 3) & 1) * 8) * STRIDE + (lane >> 4) * 16;
    int boff = ((lane >> 4) * 8 + (lane & 7)) * STRIDE + ((lane >> 3) & 1) * 16;

    float acc[2][8][4];
    #pragma unroll
    for (int sm = 0; sm < 2; sm++)
        #pragma unroll
        for (int ns = 0; ns < 8; ns++)
            #pragma unroll
            for (int j = 0; j < 4; j++) acc[sm][ns][j] = 0.f;

    auto COMPUTE = [&](int st) {
        uint32_t base = sb + st * STAGEB;
        #pragma unroll
        for (int kk = 0; kk < 64; kk += 16) {
            uint32_t ah[2][4];
            #pragma unroll
            for (int sm = 0; sm < 2; sm++)
                LDSM4(ah[sm], base + (m0 + sm * 16) * STRIDE + aoff + kk * 2);
            #pragma unroll
            for (int ns2 = 0; ns2 < 4; ns2++) {
                uint32_t bh[4];
                LDSM4(bh, base + TILEB + (n0w + ns2 * 16) * STRIDE + boff + kk * 2);
                #pragma unroll
                for (int sm = 0; sm < 2; sm++) {
                    mma_fp16(acc[sm][2 * ns2],     ah[sm], bh[0], bh[1]);
                    mma_fp16(acc[sm][2 * ns2 + 1], ah[sm], bh[2], bh[3]);
                }
            }
        }
    };

    FILL(0, 0); CP_COMMIT();
    FILL(1, 1); CP_COMMIT();
    for (int kc = 0; kc < 3; kc++) {
        CP_WAIT1();
        __syncthreads();
        COMPUTE(kc);
        if (kc < 1) FILL(2, 2);
        CP_COMMIT();
    }

    #pragma unroll
    for (int sm = 0; sm < 2; sm++)
        #pragma unroll
        for (int ns = 0; ns < 8; ns++) {
            int row0 = l0 + m0 + sm * 16 + g;
            int col  = nc * 128 + n0w + ns * 8 + 2 * t;
            if (row0 < PP2) {
                atomicAdd(&g_u2[(size_t)row0 * Dd + col],     acc[sm][ns][0]);
                atomicAdd(&g_u2[(size_t)row0 * Dd + col + 1], acc[sm][ns][1]);
            }
            if (row0 + 8 < PP2) {
                atomicAdd(&g_u2[(size_t)(row0 + 8) * Dd + col],     acc[sm][ns][2]);
                atomicAdd(&g_u2[(size_t)(row0 + 8) * Dd + col + 1], acc[sm][ns][3]);
            }
        }
}

// ---------------------------------------------------------------------------
// Masked softmax pooling reading fp16 g_Ah (compact rows). 192 threads,
// thread t owns d = 4t..4t+3 (8B loads), rows unrolled x8 (64B in flight).
// ---------------------------------------------------------------------------
__global__ __launch_bounds__(192) void k_pool(const int* __restrict__ fs,
                                              const int* __restrict__ ssp)
{
    int p   = blockIdx.y;
    int sgi = blockIdx.x;
    int f = fs[p], s2 = ssp[p];
    int lo = sgi ? f + 1 : 1;
    int hi = sgi ? s2 : f;
    int cnt = hi - lo;                      // 4..148

    __shared__ float w[152];
    __shared__ float wred[8];
    __shared__ float bc;
    int tid = threadIdx.x;
    int lane = tid & 31, wid = tid >> 5;

    const float* sc = g_scores + p * Ll + lo;

    float lm = (tid < cnt) ? sc[tid] : -1e30f;
    #pragma unroll
    for (int o = 16; o > 0; o >>= 1) lm = fmaxf(lm, __shfl_xor_sync(~0u, lm, o));
    if (lane == 0) wred[wid] = lm;
    __syncthreads();
    if (tid == 0) {
        float m = wred[0];
        #pragma unroll
        for (int j = 1; j < 6; j++) m = fmaxf(m, wred[j]);
        bc = m;
    }
    __syncthreads();
    float smax = bc;

    float le = 0.f;
    if (tid < cnt) { float e = __expf(sc[tid] - smax); w[tid] = e; le = e; }
    #pragma unroll
    for (int o = 16; o > 0; o >>= 1) le += __shfl_xor_sync(~0u, le, o);
    if (lane == 0) wred[wid] = le;
    __syncthreads();
    if (tid == 0) {
        float s = 0.f;
        #pragma unroll
        for (int j = 1; j < 6; j++) s += wred[j];
        bc = 1.0f / (s + wred[0]);
    }
    __syncthreads();
    float inv = bc;
    if (tid < cnt) w[tid] *= inv;
    __syncthreads();

    int r0 = g_poff[p] + lo;
    const char* xr = reinterpret_cast<const char*>(g_Ah) + ((size_t)r0 * Dd) * 2 + tid * 8;
    float e0 = 0.f, e1 = 0.f, e2 = 0.f, e3 = 0.f;
    int i = 0;
    for (; i + 8 <= cnt; i += 8) {
        uint2 u[8];
        #pragma unroll
        for (int j = 0; j < 8; j++)
            u[j] = *reinterpret_cast<const uint2*>(xr + (size_t)(i + j) * Dd * 2);
        #pragma unroll
        for (int j = 0; j < 8; j++) {
            float wj = w[i + j];
            float2 a0 = __half22float2(*reinterpret_cast<__half2*>(&u[j].x));
            float2 a1 = __half22float2(*reinterpret_cast<__half2*>(&u[j].y));
            e0 += wj * a0.x; e1 += wj * a0.y; e2 += wj * a1.x; e3 += wj * a1.y;
        }
    }
    for (; i < cnt; i++) {
        uint2 u0 = *reinterpret_cast<const uint2*>(xr + (size_t)i * Dd * 2);
        float w0 = w[i];
        float2 a0 = __half22float2(*reinterpret_cast<__half2*>(&u0.x));
        float2 a1 = __half22float2(*reinterpret_cast<__half2*>(&u0.y));
        e0 += w0 * a0.x; e1 += w0 * a0.y; e2 += w0 * a1.x; e3 += w0 * a1.y;
    }

    int rowi = 2 * p + sgi;
    float4* er = reinterpret_cast<float4*>(g_emb + (size_t)rowi * Dd);
    er[tid] = make_float4(e0, e1, e2, e3);
    *reinterpret_cast<uint2*>(
        reinterpret_cast<char*>(g_Eh) + ((size_t)rowi * Dd) * 2 + tid * 8) =
        make_uint2(pack2f(e0, e1), pack2f(e2, e3));
}

// ---------------------------------------------------------------------------
// out2: epilogue of GEMM2 (tanh(u2+b2)@v2 for this segment's 14 rows) +
// segment softmax + weighted sum.
// ---------------------------------------------------------------------------
__global__ __launch_bounds__(256) void k_out2(const float* __restrict__ b2,
                                              const float* __restrict__ v2,
                                              float* __restrict__ out) {
    int seg = blockIdx.x;
    int tid = threadIdx.x;
    int lane = tid & 31, wid = tid >> 5;
    __shared__ int   mem[14];
    __shared__ float sscore[14];
    __shared__ float wv[14];

    if (tid == 0) {
        int c = 0;
        for (int idx = 0; idx < PP2; idx++) {
            int pp = idx >> 1, cc = idx & 1;
            int z = pp / 56, r = pp % 56, j = r / 7, m = r % 7;
            int k = m + (m >= j ? 1 : 0);
            int sg = z * 8 + (cc == 0 ? j : k);
            if (sg == seg && c < 14) mem[c++] = idx;
        }
    }
    __syncthreads();

    #pragma unroll
    for (int ii = 0; ii < 2; ii++) {
        int i = wid + ii * 8;
        if (i < 14) {
            const float* ur = g_u2 + (size_t)mem[i] * Dd;
            float acc = 0.f;
            for (int d = lane; d < Dd; d += 32)
                acc += tanh_f(ur[d] + __ldg(&b2[d])) * __ldg(&v2[d]);
            #pragma unroll
            for (int o = 16; o > 0; o >>= 1)
                acc += __shfl_xor_sync(~0u, acc, o);
            if (lane == 0) sscore[i] = acc;
        }
    }
    __syncthreads();

    if (tid == 0) {
        float mx = -1e30f;
        for (int i = 0; i < 14; i++) mx = fmaxf(mx, sscore[i]);
        float den = 0.f;
        for (int i = 0; i < 14; i++) {
            float e = __expf(sscore[i] - mx);
            wv[i] = e;
            den += e;
        }
        float inv = 1.f / den;
        for (int i = 0; i < 14; i++) wv[i] *= inv;
    }
    __syncthreads();

    for (int d = tid; d < Dd; d += 256) {
        float a = 0.f;
        #pragma unroll
        for (int i = 0; i < 14; i++)
            a += wv[i] * g_emb[(size_t)mem[i] * Dd + d];
        out[Pp * Dd + seg * Dd + d] = a;
    }
}

// ---------------------------------------------------------------------------
// Launch
// ---------------------------------------------------------------------------
extern "C" void kernel_launch(void* const* d_in, const int* in_sizes, int n_in,
                              void* d_out, int out_size) {
    const float* x   = (const float*)d_in[0];
    const int*   fs  = (const int*)  d_in[1];
    const int*   ss  = (const int*)  d_in[2];
    const float* W1  = (const float*)d_in[3];
    const float* b1  = (const float*)d_in[4];
    const float* v1  = (const float*)d_in[5];
    const float* W2  = (const float*)d_in[7];
    const float* b2  = (const float*)d_in[8];
    const float* v2  = (const float*)d_in[9];
    float* out = (float*)d_out;

    static bool attr_done = false;
    if (!attr_done) {
        cudaFuncSetAttribute(k_gemm1,
            cudaFuncAttributeMaxDynamicSharedMemorySize, SMEM_TOT);
        cudaFuncSetAttribute(k_gemm2,
            cudaFuncAttributeMaxDynamicSharedMemorySize, SMEM_TOT);
        attr_done = true;
    }

    k_init<<<1632, 256>>>(x, ss, W1, W2, out);

    k_gemm1<<<dim3((RMAX + 127) / 128, 6), 256, SMEM_TOT>>>(b1, v1);

    k_pool<<<dim3(2, Pp), 192>>>(fs, ss);

    k_gemm2<<<dim3(4, 6, 4), 256, SMEM_TOT>>>();

    k_out2<<<Bb * Ss, 256>>>(b2, v2, out);
}

// round 16
// speedup vs baseline: 1.0745x; 1.0516x over previous
#include <cuda_runtime.h>
#include <cuda_fp16.h>
#include <cstdint>
#include <math.h>

#define Bb   4
#define Ss   8
#define Ll   350
#define Dd   768
#define Pp   224
#define PP2  448
#define RMAX (Pp * 300)        // second_sep < 300 strictly

// ---------------------------------------------------------------------------
// Scratch (static device globals; no allocation allowed)
// ---------------------------------------------------------------------------
__device__ float g_scores[Pp * Ll];
__device__ float g_emb[PP2 * Dd];
__device__ float g_u2[PP2 * Dd];       // raw GEMM2 accumulator (pre-tanh)
__device__ int   g_poff[Pp + 1];
__device__ int   g_rowmap[RMAX];
__device__ __half g_Ah[RMAX * Dd];
__device__ __half g_Eh[PP2 * Dd];
__device__ __half g_W1h[Dd * Dd];
__device__ __half g_W2h[Dd * Dd];

__device__ __forceinline__ uint32_t smem_u32(const void* p) {
    uint32_t a;
    asm("{ .reg .u64 t; cvta.to.shared.u64 t, %1; cvt.u32.u64 %0, t; }"
        : "=r"(a) : "l"(p));
    return a;
}

__device__ __forceinline__ uint32_t pack2f(float a, float b) {
    __half2 h = __float22half2_rn(make_float2(a, b));
    return *reinterpret_cast<uint32_t*>(&h);
}

__device__ __forceinline__ float tanh_f(float x) {
    float y;
    asm("tanh.approx.f32 %0, %1;" : "=f"(y) : "f"(x));
    return y;
}

__device__ __forceinline__ void mma_fp16(float* c, const uint32_t* a,
                                         uint32_t b0, uint32_t b1) {
    asm volatile(
        "mma.sync.aligned.m16n8k16.row.col.f32.f16.f16.f32 "
        "{%0,%1,%2,%3}, {%4,%5,%6,%7}, {%8,%9}, {%0,%1,%2,%3};"
        : "+f"(c[0]), "+f"(c[1]), "+f"(c[2]), "+f"(c[3])
        : "r"(a[0]), "r"(a[1]), "r"(a[2]), "r"(a[3]), "r"(b0), "r"(b1));
}

#define LDSM4(r, a) \
    asm volatile("ldmatrix.sync.aligned.m8n8.x4.shared.b16 {%0,%1,%2,%3}, [%4];" \
        : "=r"((r)[0]), "=r"((r)[1]), "=r"((r)[2]), "=r"((r)[3]) : "r"(a))

#define CP16(dst, src) \
    asm volatile("cp.async.cg.shared.global [%0], [%1], 16;" \
                 :: "r"(dst), "l"(src) : "memory")
#define CP_COMMIT() asm volatile("cp.async.commit_group;" ::: "memory")
#define CP_WAIT1()  asm volatile("cp.async.wait_group 1;"  ::: "memory")

#define BKB     128            // bytes along k per stage (64 halves)
#define STRIDE  144
#define TILEB   18432          // 128 * 144
#define STAGEB  36864          // A | B
#define NST     3
#define SMEM_TOT (NST * STAGEB + 1024)

// ---------------------------------------------------------------------------
// k_init, three block roles in one launch:
//   blocks [0,672):     zero g_scores/g_u2, pair_embeddings copy,
//                       (block 0) global prefix offsets + rowmap
//   blocks [672,960):    W transpose + fp16 convert (288 = 12x12x2)
//   blocks [960,1632):   A compact+convert (pair p, 100-row chunk), local scan
// ---------------------------------------------------------------------------
__global__ void k_init(const float* __restrict__ x, const int* __restrict__ ss,
                       const float* __restrict__ W1, const float* __restrict__ W2,
                       float* __restrict__ out) {
    int bid = blockIdx.x;
    int tid = threadIdx.x;

    if (bid < 672) {
        int i = bid * 256 + tid;
        if (i < Pp * Ll) g_scores[i] = 0.f;
        g_u2[i * 2]     = 0.f;          // 672*256*2 = 344064 = PP2*Dd exactly
        g_u2[i * 2 + 1] = 0.f;
        if (i < Pp * Dd) {
            int p = i / Dd, d = i - p * Dd;
            out[i] = x[(size_t)p * Ll * Dd + d];
        }
        if (bid == 0) {
            __shared__ int sp[Pp];
            if (tid < Pp) sp[tid] = ss[tid];
            __syncthreads();
            if (tid == 0) {
                int a = 0;
                for (int p = 0; p < Pp; p++) { int v = sp[p]; sp[p] = a; a += v; }
                g_poff[Pp] = a;
            }
            __syncthreads();
            if (tid < Pp) {
                int base = sp[tid];
                g_poff[tid] = base;
                int cnt = ss[tid];
                int src = tid * Ll;
                for (int l = 0; l < cnt; l++) g_rowmap[base + l] = src + l;
            }
        }
    } else if (bid < 960) {
        __shared__ float s[64][65];
        int b = bid - 672;              // 288 = 12 x 12 x 2
        int kb = b % 12, nb = (b / 12) % 12, z = b / 144;
        int k0 = kb * 64, n0 = nb * 64;
        const float* W = z ? W2 : W1;
        __half* OH = z ? g_W2h : g_W1h;
        int nl = tid & 63, kl = tid >> 6;
        #pragma unroll
        for (int j = 0; j < 16; j++)
            s[kl + j * 4][nl] = W[(size_t)(k0 + kl + j * 4) * Dd + n0 + nl];
        __syncthreads();
        int q = tid & 31, nr = tid >> 5;
        #pragma unroll
        for (int j = 0; j < 8; j++) {
            int n = nr + j * 8;
            size_t off = (size_t)(n0 + n) * Dd + k0 + 2 * q;
            *reinterpret_cast<uint32_t*>(reinterpret_cast<char*>(OH) + off * 2) =
                pack2f(s[2 * q][n], s[2 * q + 1][n]);
        }
    } else {
        // A conversion role: block = (p, chunk of up to 100 rows)
        __shared__ int sp[256];
        int b = bid - 960;
        int p = b % Pp, chunk = b / Pp;          // chunk 0..2
        sp[tid] = (tid < Pp) ? ss[tid] : 0;
        __syncthreads();
        #pragma unroll
        for (int o = 1; o < Pp; o <<= 1) {
            int v = sp[tid];
            if (tid >= o && tid < Pp) v += sp[tid - o];
            __syncthreads();
            sp[tid] = v;
            __syncthreads();
        }
        int base = p ? sp[p - 1] : 0;
        int cnt  = sp[p] - base;                 // = ss[p]
        int l0c  = chunk * 100;
        int lend = min(cnt, l0c + 100);
        if (tid < 192 && l0c < lend) {
            int rows = lend - l0c;
            const float* src = x + ((size_t)p * Ll + l0c) * Dd + tid * 4;
            char* dst = reinterpret_cast<char*>(g_Ah)
                      + ((size_t)(base + l0c) * Dd + tid * 4) * 2;
            int lr = 0;
            for (; lr + 4 <= rows; lr += 4) {
                float4 v0 = *reinterpret_cast<const float4*>(src + (size_t)(lr)     * Dd);
                float4 v1 = *reinterpret_cast<const float4*>(src + (size_t)(lr + 1) * Dd);
                float4 v2 = *reinterpret_cast<const float4*>(src + (size_t)(lr + 2) * Dd);
                float4 v3 = *reinterpret_cast<const float4*>(src + (size_t)(lr + 3) * Dd);
                *reinterpret_cast<uint2*>(dst + (size_t)(lr)     * Dd * 2) =
                    make_uint2(pack2f(v0.x, v0.y), pack2f(v0.z, v0.w));
                *reinterpret_cast<uint2*>(dst + (size_t)(lr + 1) * Dd * 2) =
                    make_uint2(pack2f(v1.x, v1.y), pack2f(v1.z, v1.w));
                *reinterpret_cast<uint2*>(dst + (size_t)(lr + 2) * Dd * 2) =
                    make_uint2(pack2f(v2.x, v2.y), pack2f(v2.z, v2.w));
                *reinterpret_cast<uint2*>(dst + (size_t)(lr + 3) * Dd * 2) =
                    make_uint2(pack2f(v3.x, v3.y), pack2f(v3.z, v3.w));
            }
            for (; lr < rows; lr++) {
                float4 v0 = *reinterpret_cast<const float4*>(src + (size_t)lr * Dd);
                *reinterpret_cast<uint2*>(dst + (size_t)lr * Dd * 2) =
                    make_uint2(pack2f(v0.x, v0.y), pack2f(v0.z, v0.w));
            }
        }
    }
}

// ---------------------------------------------------------------------------
// GEMM1 (scores): wave-based fused HMMA (best measured form), BK=64,
// NST=3 cp.async, ldmatrix. grid (row tiles, 6 nc), K=768 (12 stages),
// fused tanh epilogue -> atomicAdd per-row partials.
// 110KB smem -> 2 CTAs/SM co-residency (protected). Persistence: rejected
// twice (R10, R14) — do not retry. FROZEN.
// ---------------------------------------------------------------------------
__global__ __launch_bounds__(256) void k_gemm1(
    const float* __restrict__ bvec, const float* __restrict__ vvec)
{
    extern __shared__ char smem[];
    int tid = threadIdx.x;
    int l0 = blockIdx.x * 128;
    int nc = blockIdx.y;

    int R = g_poff[Pp];
    if (l0 >= R) return;

    uint32_t sb = smem_u32(smem);

    int q = tid & 7, rb = tid >> 3;
    const char *pa[4], *pb[4];
    uint32_t pd[4];
    #pragma unroll
    for (int j = 0; j < 4; j++) {
        int row = rb + j * 32;
        int gr = l0 + row; if (gr >= R) gr = R - 1;
        pa[j] = reinterpret_cast<const char*>(g_Ah + (size_t)gr * Dd) + q * 16;
        pb[j] = reinterpret_cast<const char*>(g_W1h + (size_t)(nc * 128 + row) * Dd) + q * 16;
        pd[j] = sb + row * STRIDE + q * 16;
    }

    auto FILL = [&](int s, int kc) {
        uint32_t stg = s * STAGEB;
        int ko = kc * BKB;
        #pragma unroll
        for (int j = 0; j < 4; j++) {
            CP16(pd[j] + stg,         pa[j] + ko);
            CP16(pd[j] + stg + TILEB, pb[j] + ko);
        }
    };

    int warp = tid >> 5, lane = tid & 31;
    int g = lane >> 2, t = lane & 3;
    int m0 = (warp >> 1) * 32;
    int wn = warp & 1;
    int n0w = wn * 64;

    int aoff = ((lane & 7) + ((lane >> 3) & 1) * 8) * STRIDE + (lane >> 4) * 16;
    int boff = ((lane >> 4) * 8 + (lane & 7)) * STRIDE + ((lane >> 3) & 1) * 16;

    float acc[2][8][4];
    #pragma unroll
    for (int sm = 0; sm < 2; sm++)
        #pragma unroll
        for (int ns = 0; ns < 8; ns++)
            #pragma unroll
            for (int j = 0; j < 4; j++) acc[sm][ns][j] = 0.f;

    auto COMPUTE = [&](int st) {
        uint32_t base = sb + st * STAGEB;
        #pragma unroll
        for (int kk = 0; kk < 64; kk += 16) {
            uint32_t ah[2][4];
            #pragma unroll
            for (int sm = 0; sm < 2; sm++)
                LDSM4(ah[sm], base + (m0 + sm * 16) * STRIDE + aoff + kk * 2);
            #pragma unroll
            for (int ns2 = 0; ns2 < 4; ns2++) {
                uint32_t bh[4];
                LDSM4(bh, base + TILEB + (n0w + ns2 * 16) * STRIDE + boff + kk * 2);
                #pragma unroll
                for (int sm = 0; sm < 2; sm++) {
                    mma_fp16(acc[sm][2 * ns2],     ah[sm], bh[0], bh[1]);
                    mma_fp16(acc[sm][2 * ns2 + 1], ah[sm], bh[2], bh[3]);
                }
            }
        }
    };

    FILL(0, 0); CP_COMMIT();
    FILL(1, 1); CP_COMMIT();

    for (int kc = 0; kc < 12; kc++) {
        CP_WAIT1();
        __syncthreads();
        COMPUTE(kc % 3);
        if (kc < 10) FILL((kc + 2) % 3, kc + 2);
        CP_COMMIT();
    }

    float partial[4] = {0.f, 0.f, 0.f, 0.f};
    #pragma unroll
    for (int sm = 0; sm < 2; sm++)
        #pragma unroll
        for (int ns = 0; ns < 8; ns++) {
            int col = nc * 128 + n0w + ns * 8 + 2 * t;
            float bb0 = __ldg(&bvec[col]), bb1 = __ldg(&bvec[col + 1]);
            float vv0 = __ldg(&vvec[col]), vv1 = __ldg(&vvec[col + 1]);
            partial[sm * 2 + 0] += tanh_f(acc[sm][ns][0] + bb0) * vv0
                                 + tanh_f(acc[sm][ns][1] + bb1) * vv1;
            partial[sm * 2 + 1] += tanh_f(acc[sm][ns][2] + bb0) * vv0
                                 + tanh_f(acc[sm][ns][3] + bb1) * vv1;
        }

    #pragma unroll
    for (int j = 0; j < 4; j++) {
        partial[j] += __shfl_xor_sync(0xffffffffu, partial[j], 1);
        partial[j] += __shfl_xor_sync(0xffffffffu, partial[j], 2);
    }
    float* red = reinterpret_cast<float*>(smem + NST * STAGEB);
    __syncthreads();
    if (t == 0) {
        red[wn * 128 + m0 + g]      = partial[0];
        red[wn * 128 + m0 + 8 + g]  = partial[1];
        red[wn * 128 + m0 + 16 + g] = partial[2];
        red[wn * 128 + m0 + 24 + g] = partial[3];
    }
    __syncthreads();
    if (tid < 128) {
        int r = l0 + tid;
        if (r < R) {
            float val = red[tid] + red[128 + tid];
            atomicAdd(&g_scores[g_rowmap[r]], val);
        }
    }
}

// ---------------------------------------------------------------------------
// GEMM2 (raw): grid (4 row tiles, 6 nc, 6 K-sixths), K=128 (2 stages),
// fp32 partials atomicAdd'ed to g_u2 (K-split is linear; tanh deferred).
// ---------------------------------------------------------------------------
__global__ __launch_bounds__(256) void k_gemm2() {
    extern __shared__ char smem[];
    int tid = threadIdx.x;
    int l0 = blockIdx.x * 128;
    int nc = blockIdx.y;
    int kbase = blockIdx.z * 256;        // bytes along k (128 halves per sixth)

    uint32_t sb = smem_u32(smem);

    int q = tid & 7, rb = tid >> 3;
    const char *pa[4], *pb[4];
    uint32_t pd[4];
    #pragma unroll
    for (int j = 0; j < 4; j++) {
        int row = rb + j * 32;
        int gr = l0 + row; if (gr >= PP2) gr = PP2 - 1;
        pa[j] = reinterpret_cast<const char*>(g_Eh + (size_t)gr * Dd) + kbase + q * 16;
        pb[j] = reinterpret_cast<const char*>(g_W2h + (size_t)(nc * 128 + row) * Dd) + kbase + q * 16;
        pd[j] = sb + row * STRIDE + q * 16;
    }

    auto FILL = [&](int s, int kc) {
        uint32_t stg = s * STAGEB;
        int ko = kc * BKB;
        #pragma unroll
        for (int j = 0; j < 4; j++) {
            CP16(pd[j] + stg,         pa[j] + ko);
            CP16(pd[j] + stg + TILEB, pb[j] + ko);
        }
    };

    int warp = tid >> 5, lane = tid & 31;
    int g = lane >> 2, t = lane & 3;
    int m0 = (warp >> 1) * 32;
    int wn = warp & 1;
    int n0w = wn * 64;

    int aoff = ((lane & 7) + ((lane >> 3) & 1) * 8) * STRIDE + (lane >> 4) * 16;
    int boff = ((lane >> 4) * 8 + (lane & 7)) * STRIDE + ((lane >> 3) & 1) * 16;

    float acc[2][8][4];
    #pragma unroll
    for (int sm = 0; sm < 2; sm++)
        #pragma unroll
        for (int ns = 0; ns < 8; ns++)
            #pragma unroll
            for (int j = 0; j < 4; j++) acc[sm][ns][j] = 0.f;

    auto COMPUTE = [&](int st) {
        uint32_t base = sb + st * STAGEB;
        #pragma unroll
        for (int kk = 0; kk < 64; kk += 16) {
            uint32_t ah[2][4];
            #pragma unroll
            for (int sm = 0; sm < 2; sm++)
                LDSM4(ah[sm], base + (m0 + sm * 16) * STRIDE + aoff + kk * 2);
            #pragma unroll
            for (int ns2 = 0; ns2 < 4; ns2++) {
                uint32_t bh[4];
                LDSM4(bh, base + TILEB + (n0w + ns2 * 16) * STRIDE + boff + kk * 2);
                #pragma unroll
                for (int sm = 0; sm < 2; sm++) {
                    mma_fp16(acc[sm][2 * ns2],     ah[sm], bh[0], bh[1]);
                    mma_fp16(acc[sm][2 * ns2 + 1], ah[sm], bh[2], bh[3]);
                }
            }
        }
    };

    FILL(0, 0); CP_COMMIT();
    FILL(1, 1); CP_COMMIT();
    #pragma unroll
    for (int kc = 0; kc < 2; kc++) {
        CP_WAIT1();
        __syncthreads();
        COMPUTE(kc);
        CP_COMMIT();
    }

    #pragma unroll
    for (int sm = 0; sm < 2; sm++)
        #pragma unroll
        for (int ns = 0; ns < 8; ns++) {
            int row0 = l0 + m0 + sm * 16 + g;
            int col  = nc * 128 + n0w + ns * 8 + 2 * t;
            if (row0 < PP2) {
                atomicAdd(&g_u2[(size_t)row0 * Dd + col],     acc[sm][ns][0]);
                atomicAdd(&g_u2[(size_t)row0 * Dd + col + 1], acc[sm][ns][1]);
            }
            if (row0 + 8 < PP2) {
                atomicAdd(&g_u2[(size_t)(row0 + 8) * Dd + col],     acc[sm][ns][2]);
                atomicAdd(&g_u2[(size_t)(row0 + 8) * Dd + col + 1], acc[sm][ns][3]);
            }
        }
}

// ---------------------------------------------------------------------------
// Masked softmax pooling reading fp16 g_Ah (compact rows). 192 threads,
// thread t owns d = 4t..4t+3 (8B loads), rows unrolled x8 (64B in flight).
// ---------------------------------------------------------------------------
__global__ __launch_bounds__(192) void k_pool(const int* __restrict__ fs,
                                              const int* __restrict__ ssp)
{
    int p   = blockIdx.y;
    int sgi = blockIdx.x;
    int f = fs[p], s2 = ssp[p];
    int lo = sgi ? f + 1 : 1;
    int hi = sgi ? s2 : f;
    int cnt = hi - lo;                      // 4..148

    __shared__ float w[152];
    __shared__ float wred[8];
    __shared__ float bc;
    int tid = threadIdx.x;
    int lane = tid & 31, wid = tid >> 5;

    const float* sc = g_scores + p * Ll + lo;

    float lm = (tid < cnt) ? sc[tid] : -1e30f;
    #pragma unroll
    for (int o = 16; o > 0; o >>= 1) lm = fmaxf(lm, __shfl_xor_sync(~0u, lm, o));
    if (lane == 0) wred[wid] = lm;
    __syncthreads();
    if (tid == 0) {
        float m = wred[0];
        #pragma unroll
        for (int j = 1; j < 6; j++) m = fmaxf(m, wred[j]);
        bc = m;
    }
    __syncthreads();
    float smax = bc;

    float le = 0.f;
    if (tid < cnt) { float e = __expf(sc[tid] - smax); w[tid] = e; le = e; }
    #pragma unroll
    for (int o = 16; o > 0; o >>= 1) le += __shfl_xor_sync(~0u, le, o);
    if (lane == 0) wred[wid] = le;
    __syncthreads();
    if (tid == 0) {
        float s = 0.f;
        #pragma unroll
        for (int j = 1; j < 6; j++) s += wred[j];
        bc = 1.0f / (s + wred[0]);
    }
    __syncthreads();
    float inv = bc;
    if (tid < cnt) w[tid] *= inv;
    __syncthreads();

    int r0 = g_poff[p] + lo;
    const char* xr = reinterpret_cast<const char*>(g_Ah) + ((size_t)r0 * Dd) * 2 + tid * 8;
    float e0 = 0.f, e1 = 0.f, e2 = 0.f, e3 = 0.f;
    int i = 0;
    for (; i + 8 <= cnt; i += 8) {
        uint2 u[8];
        #pragma unroll
        for (int j = 0; j < 8; j++)
            u[j] = *reinterpret_cast<const uint2*>(xr + (size_t)(i + j) * Dd * 2);
        #pragma unroll
        for (int j = 0; j < 8; j++) {
            float wj = w[i + j];
            float2 a0 = __half22float2(*reinterpret_cast<__half2*>(&u[j].x));
            float2 a1 = __half22float2(*reinterpret_cast<__half2*>(&u[j].y));
            e0 += wj * a0.x; e1 += wj * a0.y; e2 += wj * a1.x; e3 += wj * a1.y;
        }
    }
    for (; i < cnt; i++) {
        uint2 u0 = *reinterpret_cast<const uint2*>(xr + (size_t)i * Dd * 2);
        float w0 = w[i];
        float2 a0 = __half22float2(*reinterpret_cast<__half2*>(&u0.x));
        float2 a1 = __half22float2(*reinterpret_cast<__half2*>(&u0.y));
        e0 += w0 * a0.x; e1 += w0 * a0.y; e2 += w0 * a1.x; e3 += w0 * a1.y;
    }

    int rowi = 2 * p + sgi;
    float4* er = reinterpret_cast<float4*>(g_emb + (size_t)rowi * Dd);
    er[tid] = make_float4(e0, e1, e2, e3);
    *reinterpret_cast<uint2*>(
        reinterpret_cast<char*>(g_Eh) + ((size_t)rowi * Dd) * 2 + tid * 8) =
        make_uint2(pack2f(e0, e1), pack2f(e2, e3));
}

// ---------------------------------------------------------------------------
// out2: direct member enumeration (indexing is invertible; no scan),
// GEMM2 epilogue (tanh(u2+b2)@v2), segment softmax + weighted sum.
// ---------------------------------------------------------------------------
__global__ __launch_bounds__(256) void k_out2(const float* __restrict__ b2,
                                              const float* __restrict__ v2,
                                              float* __restrict__ out) {
    int seg = blockIdx.x;
    int tid = threadIdx.x;
    int lane = tid & 31, wid = tid >> 5;
    __shared__ int   mem[14];
    __shared__ float sscore[14];
    __shared__ float wv[14];

    int s = seg & 7, z = seg >> 3;
    if (tid < 7) {
        // cc=0 members: j == s, m = tid
        mem[tid] = 2 * (z * 56 + s * 7 + tid);
    } else if (tid < 14) {
        // cc=1 members: k == s, j != s
        int jj = tid - 7;
        int j = jj + (jj >= s ? 1 : 0);
        mem[tid] = 2 * (z * 56 + j * 7 + (s - (s > j ? 1 : 0))) + 1;
    }
    __syncthreads();

    #pragma unroll
    for (int ii = 0; ii < 2; ii++) {
        int i = wid + ii * 8;
        if (i < 14) {
            const float* ur = g_u2 + (size_t)mem[i] * Dd;
            float acc = 0.f;
            for (int d = lane; d < Dd; d += 32)
                acc += tanh_f(ur[d] + __ldg(&b2[d])) * __ldg(&v2[d]);
            #pragma unroll
            for (int o = 16; o > 0; o >>= 1)
                acc += __shfl_xor_sync(~0u, acc, o);
            if (lane == 0) sscore[i] = acc;
        }
    }
    __syncthreads();

    if (tid == 0) {
        float mx = -1e30f;
        for (int i = 0; i < 14; i++) mx = fmaxf(mx, sscore[i]);
        float den = 0.f;
        for (int i = 0; i < 14; i++) {
            float e = __expf(sscore[i] - mx);
            wv[i] = e;
            den += e;
        }
        float inv = 1.f / den;
        for (int i = 0; i < 14; i++) wv[i] *= inv;
    }
    __syncthreads();

    for (int d = tid; d < Dd; d += 256) {
        float a = 0.f;
        #pragma unroll
        for (int i = 0; i < 14; i++)
            a += wv[i] * g_emb[(size_t)mem[i] * Dd + d];
        out[Pp * Dd + seg * Dd + d] = a;
    }
}

// ---------------------------------------------------------------------------
// Launch
// ---------------------------------------------------------------------------
extern "C" void kernel_launch(void* const* d_in, const int* in_sizes, int n_in,
                              void* d_out, int out_size) {
    const float* x   = (const float*)d_in[0];
    const int*   fs  = (const int*)  d_in[1];
    const int*   ss  = (const int*)  d_in[2];
    const float* W1  = (const float*)d_in[3];
    const float* b1  = (const float*)d_in[4];
    const float* v1  = (const float*)d_in[5];
    const float* W2  = (const float*)d_in[7];
    const float* b2  = (const float*)d_in[8];
    const float* v2  = (const float*)d_in[9];
    float* out = (float*)d_out;

    static bool attr_done = false;
    if (!attr_done) {
        cudaFuncSetAttribute(k_gemm1,
            cudaFuncAttributeMaxDynamicSharedMemorySize, SMEM_TOT);
        cudaFuncSetAttribute(k_gemm2,
            cudaFuncAttributeMaxDynamicSharedMemorySize, SMEM_TOT);
        attr_done = true;
    }

    k_init<<<1632, 256>>>(x, ss, W1, W2, out);

    k_gemm1<<<dim3((RMAX + 127) / 128, 6), 256, SMEM_TOT>>>(b1, v1);

    k_pool<<<dim3(2, Pp), 192>>>(fs, ss);

    k_gemm2<<<dim3(4, 6, 6), 256, SMEM_TOT>>>();

    k_out2<<<Bb * Ss, 256>>>(b2, v2, out);
}